// round 2
// baseline (speedup 1.0000x reference)
#include <cuda_runtime.h>
#include <math.h>
#include <stdint.h>

#define BB 256
#define DD 512
#define PP 5
#define NC 11003
#define SEGC 6
#define SCALE_ 28.0f
#define ALPHA_ 0.6f
#define BETA_ 0.4f
#define SP_ 10.0f
#define SN_ 40.0f

#define NCHUNK 86          // ceil(11003/128)
#define NPIX (1280*4096)   // B*P * H*H

// ---------------- device scratch (static; no allocation) ----------------
__device__ float g_XN[2*BB*DD];        // rows 0..255 = vn, 256..511 = tn
__device__ float g_tnT[DD*BB];         // [d][b]
__device__ float g_penN[PP*BB*DD];     // normalized part_embed
__device__ float g_aeT[PP*DD*BB];      // [p][d][b] normalized attribute_embed, transposed
__device__ float g_invWn[NC];
__device__ float g_chunkMax[2*BB*NCHUNK];
__device__ float g_chunkSum[2*BB*NCHUNK];
__device__ float g_labLogit[2*BB];
__device__ float g_sims[PP*BB*BB];
__device__ int   g_boost1[PP*BB];
__device__ int   g_boost2[PP*BB];
__device__ int   g_vmInt, g_tmInt;     // 1 if mask stored as int32, 0 if byte
__device__ double g_accMask;
__device__ double g_accGlob;
__device__ double g_accLocal;

// ---------------- helpers ----------------
__device__ __forceinline__ float softplus_f(float x) {
    if (x > 20.f) return x;
    if (x < -20.f) return __expf(x);
    return log1pf(__expf(x));
}

__device__ __forceinline__ double blockReduceD(double v, double* sred) {
    int t = threadIdx.x;
    sred[t] = v; __syncthreads();
    for (int s = blockDim.x >> 1; s > 0; s >>= 1) {
        if (t < s) sred[t] += sred[t + s];
        __syncthreads();
    }
    return sred[0];
}

__device__ __forceinline__ bool readMask(const uint8_t* m, int idx, int isInt) {
    return isInt ? (((const int*)m)[idx] != 0) : (m[idx] != 0);
}

__global__ void init_kernel() {
    g_accMask = 0.0; g_accGlob = 0.0; g_accLocal = 0.0;
}

// Probe mask dtype: if values are int32 (0/1), all bytes at offset%4!=0 within
// the first 1280 bytes are zero. Safe to read 1280 bytes under either layout.
__global__ void detect_kernel(const uint8_t* __restrict__ vm, const uint8_t* __restrict__ tm) {
    __shared__ int s0, s1;
    if (threadIdx.x == 0) { s0 = 0; s1 = 0; }
    __syncthreads();
    int a0 = 0, a1 = 0;
    for (int i = threadIdx.x; i < PP*BB; i += 256) {
        if (i & 3) { a0 |= vm[i]; a1 |= tm[i]; }
    }
    atomicOr(&s0, a0); atomicOr(&s1, a1);
    __syncthreads();
    if (threadIdx.x == 0) { g_vmInt = (s0 == 0) ? 1 : 0; g_tmInt = (s1 == 0) ? 1 : 0; }
}

// ---------------- normalize rows (+ transposed copies for tn, ae) ----------------
__global__ void normalize_kernel(const float* __restrict__ v, const float* __restrict__ t,
                                 const float* __restrict__ pe, const float* __restrict__ ae) {
    __shared__ float sred[256];
    int b = blockIdx.x;
    const float* src;
    float* dst = nullptr;
    float* dstT = nullptr;
    int tcol = 0;
    if (b < 256) { src = v + (size_t)b*DD; dst = g_XN + (size_t)b*DD; }
    else if (b < 512) { int r = b - 256; src = t + (size_t)r*DD; dst = g_XN + (size_t)b*DD; dstT = g_tnT; tcol = r; }
    else if (b < 512 + PP*BB) { int k = b - 512; src = pe + (size_t)k*DD; dst = g_penN + (size_t)k*DD; }
    else { int k = b - 512 - PP*BB; int p = k / BB; int rr = k % BB;
           src = ae + (size_t)k*DD; dstT = g_aeT + (size_t)p*DD*BB; tcol = rr; }

    float s = 0.f;
    for (int d = threadIdx.x; d < DD; d += 256) { float x = src[d]; s += x*x; }
    sred[threadIdx.x] = s; __syncthreads();
    for (int st = 128; st > 0; st >>= 1) { if (threadIdx.x < st) sred[threadIdx.x] += sred[threadIdx.x + st]; __syncthreads(); }
    float total = sred[0];
    float inv = rsqrtf(total);
    inv = inv * (1.5f - 0.5f * total * inv * inv);  // Newton refine

    for (int d = threadIdx.x; d < DD; d += 256) {
        float x = src[d] * inv;
        if (dst)  dst[d] = x;
        if (dstT) dstT[d*BB + tcol] = x;
    }
}

// ---------------- W column inverse norms ----------------
__global__ void wnorm_kernel(const float* __restrict__ W) {
    int c = blockIdx.x * 256 + threadIdx.x;
    if (c >= NC) return;
    float s = 0.f;
    for (int d = 0; d < DD; d++) { float w = W[(size_t)d*NC + c]; s += w*w; }
    float inv = rsqrtf(s);
    inv = inv * (1.5f - 0.5f * s * inv * inv);
    g_invWn[c] = inv;
}

// ---------------- instance GEMM: 512 x 11003 x 512, tile 64x128, Kt=16 ----------------
__global__ __launch_bounds__(256) void inst_gemm(const float* __restrict__ W, const int* __restrict__ labels) {
    __shared__ __align__(16) float sm[64*129];  // union: [sX 16x64 | sW 16x128] then logits 64x129
    float* sX = sm;            // 1024 floats
    float* sW = sm + 1024;     // 2048 floats

    const int chunk = blockIdx.x, rt = blockIdx.y;
    const int colBase = chunk * 128, rowBase = rt * 64;
    const int t = threadIdx.x;
    const int tx = t & 15, ty = t >> 4;

    float acc[4][8];
    #pragma unroll
    for (int r = 0; r < 4; r++)
        #pragma unroll
        for (int c = 0; c < 8; c++) acc[r][c] = 0.f;

    for (int k0 = 0; k0 < DD; k0 += 16) {
        // load X tile (64 rows x 16 k), transposed into sX[k][row]
        {
            int r = t >> 2, kq = (t & 3) * 4;
            float4 xv = *(const float4*)&g_XN[(size_t)(rowBase + r)*DD + k0 + kq];
            sX[(kq+0)*64 + r] = xv.x;
            sX[(kq+1)*64 + r] = xv.y;
            sX[(kq+2)*64 + r] = xv.z;
            sX[(kq+3)*64 + r] = xv.w;
        }
        // load W tile (16 k x 128 cols)
        #pragma unroll
        for (int j = 0; j < 8; j++) {
            int idx = j * 256 + t;
            int kk = idx >> 7, c = idx & 127;
            int col = colBase + c;
            sW[kk*128 + c] = (col < NC) ? W[(size_t)(k0+kk)*NC + col] : 0.f;
        }
        __syncthreads();
        #pragma unroll
        for (int kk = 0; kk < 16; kk++) {
            float4 av = *(const float4*)&sX[kk*64 + ty*4];
            float4 b0 = *(const float4*)&sW[kk*128 + tx*8];
            float4 b1 = *(const float4*)&sW[kk*128 + tx*8 + 4];
            float a[4] = {av.x, av.y, av.z, av.w};
            float bv[8] = {b0.x, b0.y, b0.z, b0.w, b1.x, b1.y, b1.z, b1.w};
            #pragma unroll
            for (int r = 0; r < 4; r++)
                #pragma unroll
                for (int c = 0; c < 8; c++) acc[r][c] += a[r] * bv[c];
        }
        __syncthreads();
    }

    // epilogue: scaled logits into smem (padded stride 129 to dodge bank conflicts)
    float* L = sm;
    #pragma unroll
    for (int r = 0; r < 4; r++) {
        #pragma unroll
        for (int c = 0; c < 8; c++) {
            int col = colBase + tx*8 + c;
            float lg = (col < NC) ? (SCALE_ * acc[r][c] * g_invWn[col]) : -INFINITY;
            L[(ty*4 + r)*129 + tx*8 + c] = lg;
        }
    }
    __syncthreads();

    if (t < 64) {
        int gr = rowBase + t;
        float m = -INFINITY;
        for (int c = 0; c < 128; c++) m = fmaxf(m, L[t*129 + c]);
        float s = 0.f;
        for (int c = 0; c < 128; c++) {
            float x = L[t*129 + c];
            if (x != -INFINITY) s += __expf(x - m);
        }
        g_chunkMax[gr*NCHUNK + chunk] = m;
        g_chunkSum[gr*NCHUNK + chunk] = s;
        int lab = labels[gr & 255];
        if (lab >= colBase && lab < colBase + 128)
            g_labLogit[gr] = L[t*129 + (lab - colBase)];
    }
}

// ---------------- instance loss reduce: chunked logsumexp ----------------
__global__ void inst_reduce(float* __restrict__ out) {
    __shared__ double sred[512];
    int t = threadIdx.x;  // = row, 512 rows
    float m = -INFINITY;
    for (int j = 0; j < NCHUNK; j++) m = fmaxf(m, g_chunkMax[t*NCHUNK + j]);
    float s = 0.f;
    for (int j = 0; j < NCHUNK; j++) s += g_chunkSum[t*NCHUNK + j] * __expf(g_chunkMax[t*NCHUNK + j] - m);
    float lse = m + logf(s);
    double v = (double)(lse - g_labLogit[t]);
    double tot = blockReduceD(v, sred);
    if (t == 0) out[0] = (float)(tot / 256.0);
}

// ---------------- mask loss: per-pixel 6-way CE ----------------
__global__ void mask_kernel(const float* __restrict__ seg, const int* __restrict__ masks) {
    __shared__ double sred[256];
    long long pix = (long long)blockIdx.x * 256 + threadIdx.x;
    double v = 0.0;
    if (pix < NPIX) {
        int n = (int)(pix >> 12);
        int hw = (int)(pix & 4095);
        const float* base = seg + (size_t)n * SEGC * 4096 + hw;
        float x[SEGC];
        float m = -INFINITY;
        #pragma unroll
        for (int c = 0; c < SEGC; c++) { x[c] = base[(size_t)c*4096]; m = fmaxf(m, x[c]); }
        float s = 0.f;
        #pragma unroll
        for (int c = 0; c < SEGC; c++) s += __expf(x[c] - m);
        int cls = masks[pix];
        v = (double)(m + logf(s) - x[cls]);
    }
    double tot = blockReduceD(v, sred);
    if (threadIdx.x == 0) atomicAdd(&g_accMask, tot);
}

// ---------------- global align: fused 256x256x512 GEMM + softplus sum ----------------
__global__ __launch_bounds__(256) void global_kernel(const int* __restrict__ labels) {
    __shared__ float sV[DD*17];     // 16 rows of vn, padded
    __shared__ double sred[256];
    int rg = blockIdx.x;            // 0..15 -> rows rg*16..+15
    int j = threadIdx.x;            // col

    for (int idx = j; idx < 16*DD; idx += 256) {
        int rr = idx / DD, d = idx % DD;
        sV[d*17 + rr] = g_XN[(size_t)(rg*16 + rr)*DD + d];
    }
    __syncthreads();

    float acc[16];
    #pragma unroll
    for (int rr = 0; rr < 16; rr++) acc[rr] = 0.f;
    for (int d = 0; d < DD; d++) {
        float b = g_tnT[d*BB + j];
        #pragma unroll
        for (int rr = 0; rr < 16; rr++) acc[rr] += sV[d*17 + rr] * b;
    }

    int labj = labels[j];
    double lsum = 0.0;
    #pragma unroll
    for (int rr = 0; rr < 16; rr++) {
        int row = rg*16 + rr;
        bool match = (labels[row] == labj);
        float s = acc[rr];
        float val = match ? softplus_f(-SP_ * (s - ALPHA_)) : softplus_f(SN_ * (s - BETA_));
        lsum += (double)val;
    }
    double tot = blockReduceD(lsum, sred);
    if (j == 0) atomicAdd(&g_accGlob, tot);
}

// ---------------- part sims: 5 x (256x256x512) ----------------
__global__ __launch_bounds__(256) void sims_kernel() {
    __shared__ float sP[DD*17];
    int rg = blockIdx.x;    // 0..15
    int p = blockIdx.y;     // 0..4
    int j = threadIdx.x;

    for (int idx = j; idx < 16*DD; idx += 256) {
        int rr = idx / DD, d = idx % DD;
        sP[d*17 + rr] = g_penN[((size_t)p*BB + rg*16 + rr)*DD + d];
    }
    __syncthreads();

    float acc[16];
    #pragma unroll
    for (int rr = 0; rr < 16; rr++) acc[rr] = 0.f;
    const float* aT = g_aeT + (size_t)p*DD*BB;
    for (int d = 0; d < DD; d++) {
        float b = aT[d*BB + j];
        #pragma unroll
        for (int rr = 0; rr < 16; rr++) acc[rr] += sP[d*17 + rr] * b;
    }
    float* S = g_sims + (size_t)p*BB*BB;
    #pragma unroll
    for (int rr = 0; rr < 16; rr++) S[(size_t)(rg*16 + rr)*BB + j] = acc[rr];
}

// ---------------- boost via rank counts (no sorting needed) ----------------
__global__ void boost_kernel() {
    __shared__ float srow[BB], scol[BB];
    int p = blockIdx.x;
    int c = threadIdx.x;
    const float* S = g_sims + (size_t)p*BB*BB;
    srow[c] = S[(size_t)p*BB + c];   // row p
    scol[c] = S[(size_t)c*BB + p];   // col p
    __syncthreads();

    // boost1[c]: (p,c) in top-8 of row p AND (p,c) in top-8 of column c
    float vr = srow[c];
    int cnt = 0;
    for (int k = 0; k < BB; k++) { float o = srow[k]; cnt += (o > vr) || (o == vr && k < c); }
    bool inRow = cnt < 8;
    cnt = 0;
    for (int r = 0; r < BB; r++) { float o = S[(size_t)r*BB + c]; cnt += (o > vr) || (o == vr && r < p); }
    bool inCol = cnt < 8;
    g_boost1[p*BB + c] = (inRow && inCol) ? 1 : 0;

    // boost2[c] (c as row index r'): (r',p) in top-8 of column p AND (r',p) in top-8 of row r'
    float vc = scol[c];
    cnt = 0;
    for (int k = 0; k < BB; k++) { float o = scol[k]; cnt += (o > vc) || (o == vc && k < c); }
    bool inColP = cnt < 8;
    cnt = 0;
    for (int cc = 0; cc < BB; cc++) { float o = S[(size_t)c*BB + cc]; cnt += (o > vc) || (o == vc && cc < p); }
    bool inRowR = cnt < 8;
    g_boost2[p*BB + c] = (inColP && inRowR) ? 1 : 0;
}

// ---------------- local align loss (b1 + b2 re-indexed onto one pass) ----------------
__global__ void local_kernel(const int* __restrict__ labels,
                             const uint8_t* __restrict__ vmask,
                             const uint8_t* __restrict__ tmask) {
    __shared__ double sred[256];
    int r = blockIdx.x;   // 0..255
    int p = blockIdx.y;   // 0..4
    int c = threadIdx.x;

    int vmInt = g_vmInt, tmInt = g_tmInt;
    float s = g_sims[((size_t)p*BB + r)*BB + c];
    bool match = (labels[r] == labels[c]);
    float Lp = softplus_f(-SP_ * (s - ALPHA_));
    float Ln = softplus_f(SN_ * (s - BETA_));

    bool pmr = readMask(vmask, r*PP + p, vmInt);
    bool pmc = readMask(vmask, c*PP + p, vmInt);
    bool amc = readMask(tmask, c*PP + p, tmInt);

    double val = 0.0;
    // b1 term: selector match|boost1[c], weight pm[r]&am[c]
    if (pmr && amc) val += (double)((match || g_boost1[p*BB + c]) ? Lp : Ln);
    // b2 term (re-indexed): selector match|boost2[r], weight pm[r]&pm[c]&am[c]
    if (pmr && pmc && amc) val += (double)((match || g_boost2[p*BB + r]) ? Lp : Ln);

    double tot = blockReduceD(val, sred);
    if (c == 0) atomicAdd(&g_accLocal, tot);
}

// ---------------- finalize ----------------
__global__ void finalize_kernel(float* __restrict__ out) {
    out[1] = (float)(5.0 * g_accMask / ((double)NPIX));
    out[2] = (float)(2.0 * g_accGlob / 256.0);
    out[3] = (float)(g_accLocal / (256.0 * 5.0));
}

// ---------------- launch ----------------
extern "C" void kernel_launch(void* const* d_in, const int* in_sizes, int n_in,
                              void* d_out, int out_size) {
    const float* visual    = (const float*)d_in[0];
    const float* textual   = (const float*)d_in[1];
    const float* part      = (const float*)d_in[2];
    const float* attribute = (const float*)d_in[3];
    const float* seg       = (const float*)d_in[4];
    const float* W         = (const float*)d_in[5];
    const int*   labels    = (const int*)d_in[6];
    const int*   masks     = (const int*)d_in[7];
    const uint8_t* vmask   = (const uint8_t*)d_in[8];
    const uint8_t* tmask   = (const uint8_t*)d_in[9];
    float* out = (float*)d_out;

    init_kernel<<<1, 1>>>();
    detect_kernel<<<1, 256>>>(vmask, tmask);
    normalize_kernel<<<512 + 2*PP*BB, 256>>>(visual, textual, part, attribute);
    wnorm_kernel<<<(NC + 255) / 256, 256>>>(W);
    inst_gemm<<<dim3(NCHUNK, 8), 256>>>(W, labels);
    inst_reduce<<<1, 512>>>(out);
    mask_kernel<<<NPIX / 256, 256>>>(seg, masks);
    global_kernel<<<16, 256>>>(labels);
    sims_kernel<<<dim3(16, PP), 256>>>();
    boost_kernel<<<PP, 256>>>();
    local_kernel<<<dim3(BB, PP), 256>>>(labels, vmask, tmask);
    finalize_kernel<<<1, 1>>>(out);
}

// round 4
// speedup vs baseline: 1.1487x; 1.1487x over previous
#include <cuda_runtime.h>
#include <cuda_bf16.h>
#include <math.h>
#include <stdint.h>

#define BB 256
#define DD 512
#define PP 5
#define NC 11003
#define NCPAD 11008
#define SEGC 6
#define SCALE_ 28.0f
#define ALPHA_ 0.6f
#define BETA_ 0.4f
#define SP_ 10.0f
#define SN_ 40.0f

#define NCHUNK 172         // ceil(11008/64)
#define NPIX (1280*4096)   // B*P * H*H

// ---------------- device scratch (static; no allocation) ----------------
__device__ float g_XN[2*BB*DD];        // rows 0..255 = vn, 256..511 = tn
__device__ float g_tnT[DD*BB];         // [d][b]
__device__ float g_penN[PP*BB*DD];     // normalized part_embed
__device__ float g_aeT[PP*DD*BB];      // [p][d][b] normalized attribute_embed, transposed
__device__ float g_invWn[NC];
__device__ __nv_bfloat16 g_Ahi[2*BB*DD];   // XN hi
__device__ __nv_bfloat16 g_Alo[2*BB*DD];   // XN lo
__device__ __nv_bfloat16 g_Bhi[NCPAD*DD];  // W^T hi  [c][d]
__device__ __nv_bfloat16 g_Blo[NCPAD*DD];  // W^T lo
__device__ float g_chunkMax[2*BB*NCHUNK];
__device__ float g_chunkSum[2*BB*NCHUNK];
__device__ float g_labLogit[2*BB];
__device__ float g_sims[PP*BB*BB];
__device__ int   g_boost1[PP*BB];
__device__ int   g_boost2[PP*BB];
__device__ int   g_vmInt, g_tmInt;
__device__ double g_accMask;
__device__ double g_accGlob;
__device__ double g_accLocal;

// ---------------- math helpers ----------------
__device__ __forceinline__ float softplus_f(float x) {
    if (x > 20.f) return x;
    if (x < -20.f) return __expf(x);
    return log1pf(__expf(x));
}
__device__ __forceinline__ double blockReduceD(double v, double* sred) {
    int t = threadIdx.x;
    sred[t] = v; __syncthreads();
    for (int s = blockDim.x >> 1; s > 0; s >>= 1) {
        if (t < s) sred[t] += sred[t + s];
        __syncthreads();
    }
    return sred[0];
}
__device__ __forceinline__ bool readMask(const uint8_t* m, int idx, int isInt) {
    return isInt ? (((const int*)m)[idx] != 0) : (m[idx] != 0);
}

// bf16 HMMA: D(16x8,f32) += A(16x16,bf16) * B(16x8,bf16)
__device__ __forceinline__ void mma_bf16(float* c, const uint32_t* a, const uint32_t* b) {
    asm volatile(
        "mma.sync.aligned.m16n8k16.row.col.f32.bf16.bf16.f32 "
        "{%0,%1,%2,%3}, {%4,%5,%6,%7}, {%8,%9}, {%0,%1,%2,%3};"
        : "+f"(c[0]), "+f"(c[1]), "+f"(c[2]), "+f"(c[3])
        : "r"(a[0]), "r"(a[1]), "r"(a[2]), "r"(a[3]), "r"(b[0]), "r"(b[1]));
}

__global__ void init_kernel() {
    g_accMask = 0.0; g_accGlob = 0.0; g_accLocal = 0.0;
}

__global__ void detect_kernel(const uint8_t* __restrict__ vm, const uint8_t* __restrict__ tm) {
    __shared__ int s0, s1;
    if (threadIdx.x == 0) { s0 = 0; s1 = 0; }
    __syncthreads();
    int a0 = 0, a1 = 0;
    for (int i = threadIdx.x; i < PP*BB; i += 256) {
        if (i & 3) { a0 |= vm[i]; a1 |= tm[i]; }
    }
    atomicOr(&s0, a0); atomicOr(&s1, a1);
    __syncthreads();
    if (threadIdx.x == 0) { g_vmInt = (s0 == 0) ? 1 : 0; g_tmInt = (s1 == 0) ? 1 : 0; }
}

// ---------------- normalize rows (+ transposed copies for tn, ae) ----------------
__global__ void normalize_kernel(const float* __restrict__ v, const float* __restrict__ t,
                                 const float* __restrict__ pe, const float* __restrict__ ae) {
    __shared__ float sred[256];
    int b = blockIdx.x;
    const float* src;
    float* dst = nullptr;
    float* dstT = nullptr;
    int tcol = 0;
    if (b < 256) { src = v + (size_t)b*DD; dst = g_XN + (size_t)b*DD; }
    else if (b < 512) { int r = b - 256; src = t + (size_t)r*DD; dst = g_XN + (size_t)b*DD; dstT = g_tnT; tcol = r; }
    else if (b < 512 + PP*BB) { int k = b - 512; src = pe + (size_t)k*DD; dst = g_penN + (size_t)k*DD; }
    else { int k = b - 512 - PP*BB; int p = k / BB; int rr = k % BB;
           src = ae + (size_t)k*DD; dstT = g_aeT + (size_t)p*DD*BB; tcol = rr; }

    float s = 0.f;
    for (int d = threadIdx.x; d < DD; d += 256) { float x = src[d]; s += x*x; }
    sred[threadIdx.x] = s; __syncthreads();
    for (int st = 128; st > 0; st >>= 1) { if (threadIdx.x < st) sred[threadIdx.x] += sred[threadIdx.x + st]; __syncthreads(); }
    float total = sred[0];
    float inv = rsqrtf(total);
    inv = inv * (1.5f - 0.5f * total * inv * inv);

    for (int d = threadIdx.x; d < DD; d += 256) {
        float x = src[d] * inv;
        if (dst)  dst[d] = x;
        if (dstT) dstT[d*BB + tcol] = x;
    }
}

// ---------------- convert XN -> bf16 hi/lo ----------------
__global__ void cvtA_kernel() {
    int i = blockIdx.x * 256 + threadIdx.x;
    float v = g_XN[i];
    __nv_bfloat16 hi = __float2bfloat16(v);
    float rem = v - __bfloat162float(hi);
    g_Ahi[i] = hi;
    g_Alo[i] = __float2bfloat16(rem);
}

// ---------------- transpose W -> bf16 hi/lo [c][d], pad cols to 11008 ----------------
__global__ void cvtW_kernel(const float* __restrict__ W) {
    __shared__ float tile[32][33];
    int tx = threadIdx.x & 31, ty = threadIdx.x >> 5;  // ty 0..7
    int c0 = blockIdx.x * 32, d0 = blockIdx.y * 32;
    #pragma unroll
    for (int i = 0; i < 4; i++) {
        int d = d0 + ty + i*8, c = c0 + tx;
        tile[ty + i*8][tx] = (c < NC) ? W[(size_t)d*NC + c] : 0.f;
    }
    __syncthreads();
    #pragma unroll
    for (int i = 0; i < 4; i++) {
        int cl = ty + i*8;
        int c = c0 + cl, d = d0 + tx;
        float v = tile[tx][cl];
        __nv_bfloat16 hi = __float2bfloat16(v);
        float rem = v - __bfloat162float(hi);
        g_Bhi[(size_t)c*DD + d] = hi;
        g_Blo[(size_t)c*DD + d] = __float2bfloat16(rem);
    }
}

// ---------------- W column inverse norms (4-way split over d) ----------------
__global__ void wnorm_kernel(const float* __restrict__ W) {
    __shared__ float sm2[64][5];
    int cl = threadIdx.x >> 2, q = threadIdx.x & 3;
    int c = blockIdx.x * 64 + cl;
    float s = 0.f;
    if (c < NC) {
        for (int d = q*128; d < q*128 + 128; d++) { float w = W[(size_t)d*NC + c]; s += w*w; }
    }
    sm2[cl][q] = s;
    __syncthreads();
    if (q == 0 && c < NC) {
        float tot = sm2[cl][0] + sm2[cl][1] + sm2[cl][2] + sm2[cl][3];
        float inv = rsqrtf(tot);
        inv = inv * (1.5f - 0.5f * tot * inv * inv);
        g_invWn[c] = inv;
    }
}

// ---------------- instance GEMM via mma.sync bf16 hi/lo: 512 x 11008 x 512 ----------------
// CTA tile: M=128 x N=64, K staged 64 at a time in smem. 8 warps, each 16 rows x 64 cols.
// smem rows padded to 72 bf16 (36 words) -> conflict-free fragment loads.
#define SA_STRIDE 72
#define SMEM_AH 0
#define SMEM_AL 18432
#define SMEM_BH 36864
#define SMEM_BL 46080
#define GEMM_SMEM 55296

__global__ __launch_bounds__(256, 1) void inst_gemm_mma(const int* __restrict__ labels) {
    extern __shared__ __align__(16) char smem[];
    __nv_bfloat16* sAh = (__nv_bfloat16*)(smem + SMEM_AH);
    __nv_bfloat16* sAl = (__nv_bfloat16*)(smem + SMEM_AL);
    __nv_bfloat16* sBh = (__nv_bfloat16*)(smem + SMEM_BH);
    __nv_bfloat16* sBl = (__nv_bfloat16*)(smem + SMEM_BL);

    const int chunk = blockIdx.x;              // 0..171, cols chunk*64
    const int rowBase = blockIdx.y * 128;      // 0..3
    const int colBase = chunk * 64;
    const int t = threadIdx.x;
    const int w = t >> 5, lane = t & 31;
    const int g = lane >> 2, tig = lane & 3;

    float acc[8][4];
    #pragma unroll
    for (int nf = 0; nf < 8; nf++)
        #pragma unroll
        for (int q = 0; q < 4; q++) acc[nf][q] = 0.f;

    for (int kc = 0; kc < 8; kc++) {
        int k0g = kc * 64;
        // A tiles: 128 rows x 32 u32
        for (int idx = t; idx < 128*32; idx += 256) {
            int row = idx >> 5, j = idx & 31;
            ((uint32_t*)sAh)[row*36 + j] = ((const uint32_t*)(g_Ahi + (size_t)(rowBase+row)*DD + k0g))[j];
            ((uint32_t*)sAl)[row*36 + j] = ((const uint32_t*)(g_Alo + (size_t)(rowBase+row)*DD + k0g))[j];
        }
        // B tiles: 64 rows x 32 u32
        for (int idx = t; idx < 64*32; idx += 256) {
            int row = idx >> 5, j = idx & 31;
            ((uint32_t*)sBh)[row*36 + j] = ((const uint32_t*)(g_Bhi + (size_t)(colBase+row)*DD + k0g))[j];
            ((uint32_t*)sBl)[row*36 + j] = ((const uint32_t*)(g_Blo + (size_t)(colBase+row)*DD + k0g))[j];
        }
        __syncthreads();

        #pragma unroll
        for (int ks = 0; ks < 4; ks++) {
            int k0 = ks * 16;
            int rb = w * 16;
            uint32_t ah[4], al[4];
            ah[0] = *(const uint32_t*)&sAh[(rb+g  )*SA_STRIDE + k0     + tig*2];
            ah[1] = *(const uint32_t*)&sAh[(rb+g+8)*SA_STRIDE + k0     + tig*2];
            ah[2] = *(const uint32_t*)&sAh[(rb+g  )*SA_STRIDE + k0 + 8 + tig*2];
            ah[3] = *(const uint32_t*)&sAh[(rb+g+8)*SA_STRIDE + k0 + 8 + tig*2];
            al[0] = *(const uint32_t*)&sAl[(rb+g  )*SA_STRIDE + k0     + tig*2];
            al[1] = *(const uint32_t*)&sAl[(rb+g+8)*SA_STRIDE + k0     + tig*2];
            al[2] = *(const uint32_t*)&sAl[(rb+g  )*SA_STRIDE + k0 + 8 + tig*2];
            al[3] = *(const uint32_t*)&sAl[(rb+g+8)*SA_STRIDE + k0 + 8 + tig*2];

            uint32_t bh[8][2], bl[8][2];
            #pragma unroll
            for (int nf = 0; nf < 8; nf++) {
                int cb = nf*8 + g;
                bh[nf][0] = *(const uint32_t*)&sBh[cb*SA_STRIDE + k0     + tig*2];
                bh[nf][1] = *(const uint32_t*)&sBh[cb*SA_STRIDE + k0 + 8 + tig*2];
                bl[nf][0] = *(const uint32_t*)&sBl[cb*SA_STRIDE + k0     + tig*2];
                bl[nf][1] = *(const uint32_t*)&sBl[cb*SA_STRIDE + k0 + 8 + tig*2];
            }
            #pragma unroll
            for (int nf = 0; nf < 8; nf++) {
                mma_bf16(acc[nf], ah, bh[nf]);   // hi*hi
                mma_bf16(acc[nf], al, bh[nf]);   // lo*hi
                mma_bf16(acc[nf], ah, bl[nf]);   // hi*lo
            }
        }
        __syncthreads();
    }

    // epilogue: each warp owns rows w*16..w*16+15; row halves h=0 (g) and h=1 (g+8).
    #pragma unroll
    for (int h = 0; h < 2; h++) {
        int rowl = w*16 + g + h*8;
        int gr = rowBase + rowl;
        int lab = labels[gr & 255];
        float lg[8][2];
        float m = -INFINITY;
        #pragma unroll
        for (int nf = 0; nf < 8; nf++) {
            #pragma unroll
            for (int j = 0; j < 2; j++) {
                int col = colBase + nf*8 + tig*2 + j;
                float x;
                if (col < NC) {
                    x = SCALE_ * acc[nf][h*2 + j] * g_invWn[col];
                    if (col == lab) g_labLogit[gr] = x;
                } else {
                    x = -INFINITY;
                }
                lg[nf][j] = x;
                m = fmaxf(m, x);
            }
        }
        m = fmaxf(m, __shfl_xor_sync(0xffffffffu, m, 1));
        m = fmaxf(m, __shfl_xor_sync(0xffffffffu, m, 2));
        float s = 0.f;
        #pragma unroll
        for (int nf = 0; nf < 8; nf++)
            #pragma unroll
            for (int j = 0; j < 2; j++) s += __expf(lg[nf][j] - m);
        s += __shfl_xor_sync(0xffffffffu, s, 1);
        s += __shfl_xor_sync(0xffffffffu, s, 2);
        if (tig == 0) {
            g_chunkMax[gr*NCHUNK + chunk] = m;
            g_chunkSum[gr*NCHUNK + chunk] = s;
        }
    }
}

// ---------------- instance loss reduce: chunked logsumexp ----------------
__global__ void inst_reduce(float* __restrict__ out) {
    __shared__ double sred[512];
    int t = threadIdx.x;
    float m = -INFINITY;
    for (int j = 0; j < NCHUNK; j++) m = fmaxf(m, g_chunkMax[t*NCHUNK + j]);
    float s = 0.f;
    for (int j = 0; j < NCHUNK; j++) s += g_chunkSum[t*NCHUNK + j] * __expf(g_chunkMax[t*NCHUNK + j] - m);
    float lse = m + logf(s);
    double v = (double)(lse - g_labLogit[t]);
    double tot = blockReduceD(v, sred);
    if (t == 0) out[0] = (float)(tot / 256.0);
}

// ---------------- mask loss ----------------
__global__ void mask_kernel(const float* __restrict__ seg, const int* __restrict__ masks) {
    __shared__ double sred[256];
    long long pix = (long long)blockIdx.x * 256 + threadIdx.x;
    double v = 0.0;
    if (pix < NPIX) {
        int n = (int)(pix >> 12);
        int hw = (int)(pix & 4095);
        const float* base = seg + (size_t)n * SEGC * 4096 + hw;
        float x[SEGC];
        float m = -INFINITY;
        #pragma unroll
        for (int c = 0; c < SEGC; c++) { x[c] = base[(size_t)c*4096]; m = fmaxf(m, x[c]); }
        float s = 0.f;
        #pragma unroll
        for (int c = 0; c < SEGC; c++) s += __expf(x[c] - m);
        int cls = masks[pix];
        v = (double)(m + logf(s) - x[cls]);
    }
    double tot = blockReduceD(v, sred);
    if (threadIdx.x == 0) atomicAdd(&g_accMask, tot);
}

// ---------------- global align ----------------
__global__ __launch_bounds__(256) void global_kernel(const int* __restrict__ labels) {
    __shared__ float sV[DD*17];
    __shared__ double sred[256];
    int rg = blockIdx.x;
    int j = threadIdx.x;

    for (int idx = j; idx < 16*DD; idx += 256) {
        int rr = idx / DD, d = idx % DD;
        sV[d*17 + rr] = g_XN[(size_t)(rg*16 + rr)*DD + d];
    }
    __syncthreads();

    float acc[16];
    #pragma unroll
    for (int rr = 0; rr < 16; rr++) acc[rr] = 0.f;
    for (int d = 0; d < DD; d++) {
        float b = g_tnT[d*BB + j];
        #pragma unroll
        for (int rr = 0; rr < 16; rr++) acc[rr] += sV[d*17 + rr] * b;
    }

    int labj = labels[j];
    double lsum = 0.0;
    #pragma unroll
    for (int rr = 0; rr < 16; rr++) {
        int row = rg*16 + rr;
        bool match = (labels[row] == labj);
        float s = acc[rr];
        float val = match ? softplus_f(-SP_ * (s - ALPHA_)) : softplus_f(SN_ * (s - BETA_));
        lsum += (double)val;
    }
    double tot = blockReduceD(lsum, sred);
    if (j == 0) atomicAdd(&g_accGlob, tot);
}

// ---------------- part sims ----------------
__global__ __launch_bounds__(256) void sims_kernel() {
    __shared__ float sP[DD*17];
    int rg = blockIdx.x;
    int p = blockIdx.y;
    int j = threadIdx.x;

    for (int idx = j; idx < 16*DD; idx += 256) {
        int rr = idx / DD, d = idx % DD;
        sP[d*17 + rr] = g_penN[((size_t)p*BB + rg*16 + rr)*DD + d];
    }
    __syncthreads();

    float acc[16];
    #pragma unroll
    for (int rr = 0; rr < 16; rr++) acc[rr] = 0.f;
    const float* aT = g_aeT + (size_t)p*DD*BB;
    for (int d = 0; d < DD; d++) {
        float b = aT[d*BB + j];
        #pragma unroll
        for (int rr = 0; rr < 16; rr++) acc[rr] += sP[d*17 + rr] * b;
    }
    float* S = g_sims + (size_t)p*BB*BB;
    #pragma unroll
    for (int rr = 0; rr < 16; rr++) S[(size_t)(rg*16 + rr)*BB + j] = acc[rr];
}

// ---------------- boost via rank counts ----------------
__global__ void boost_kernel() {
    __shared__ float srow[BB], scol[BB];
    int p = blockIdx.x;
    int c = threadIdx.x;
    const float* S = g_sims + (size_t)p*BB*BB;
    srow[c] = S[(size_t)p*BB + c];
    scol[c] = S[(size_t)c*BB + p];
    __syncthreads();

    float vr = srow[c];
    int cnt = 0;
    for (int k = 0; k < BB; k++) { float o = srow[k]; cnt += (o > vr) || (o == vr && k < c); }
    bool inRow = cnt < 8;
    cnt = 0;
    for (int r = 0; r < BB; r++) { float o = S[(size_t)r*BB + c]; cnt += (o > vr) || (o == vr && r < p); }
    bool inCol = cnt < 8;
    g_boost1[p*BB + c] = (inRow && inCol) ? 1 : 0;

    float vc = scol[c];
    cnt = 0;
    for (int k = 0; k < BB; k++) { float o = scol[k]; cnt += (o > vc) || (o == vc && k < c); }
    bool inColP = cnt < 8;
    cnt = 0;
    for (int cc = 0; cc < BB; cc++) { float o = S[(size_t)c*BB + cc]; cnt += (o > vc) || (o == vc && cc < p); }
    bool inRowR = cnt < 8;
    g_boost2[p*BB + c] = (inColP && inRowR) ? 1 : 0;
}

// ---------------- local align loss ----------------
__global__ void local_kernel(const int* __restrict__ labels,
                             const uint8_t* __restrict__ vmask,
                             const uint8_t* __restrict__ tmask) {
    __shared__ double sred[256];
    int r = blockIdx.x;
    int p = blockIdx.y;
    int c = threadIdx.x;

    int vmInt = g_vmInt, tmInt = g_tmInt;
    float s = g_sims[((size_t)p*BB + r)*BB + c];
    bool match = (labels[r] == labels[c]);
    float Lp = softplus_f(-SP_ * (s - ALPHA_));
    float Ln = softplus_f(SN_ * (s - BETA_));

    bool pmr = readMask(vmask, r*PP + p, vmInt);
    bool pmc = readMask(vmask, c*PP + p, vmInt);
    bool amc = readMask(tmask, c*PP + p, tmInt);

    double val = 0.0;
    if (pmr && amc) val += (double)((match || g_boost1[p*BB + c]) ? Lp : Ln);
    if (pmr && pmc && amc) val += (double)((match || g_boost2[p*BB + r]) ? Lp : Ln);

    double tot = blockReduceD(val, sred);
    if (c == 0) atomicAdd(&g_accLocal, tot);
}

__global__ void finalize_kernel(float* __restrict__ out) {
    out[1] = (float)(5.0 * g_accMask / ((double)NPIX));
    out[2] = (float)(2.0 * g_accGlob / 256.0);
    out[3] = (float)(g_accLocal / (256.0 * 5.0));
}

// ---------------- launch ----------------
extern "C" void kernel_launch(void* const* d_in, const int* in_sizes, int n_in,
                              void* d_out, int out_size) {
    const float* visual    = (const float*)d_in[0];
    const float* textual   = (const float*)d_in[1];
    const float* part      = (const float*)d_in[2];
    const float* attribute = (const float*)d_in[3];
    const float* seg       = (const float*)d_in[4];
    const float* W         = (const float*)d_in[5];
    const int*   labels    = (const int*)d_in[6];
    const int*   masks     = (const int*)d_in[7];
    const uint8_t* vmask   = (const uint8_t*)d_in[8];
    const uint8_t* tmask   = (const uint8_t*)d_in[9];
    float* out = (float*)d_out;

    static int smem_set = 0;
    if (!smem_set) {
        cudaFuncSetAttribute(inst_gemm_mma, cudaFuncAttributeMaxDynamicSharedMemorySize, GEMM_SMEM);
        smem_set = 1;
    }

    init_kernel<<<1, 1>>>();
    detect_kernel<<<1, 256>>>(vmask, tmask);
    normalize_kernel<<<512 + 2*PP*BB, 256>>>(visual, textual, part, attribute);
    cvtA_kernel<<<2*BB*DD/256, 256>>>();
    cvtW_kernel<<<dim3(NCPAD/32, DD/32), 256>>>(W);
    wnorm_kernel<<<(NC + 63) / 64, 256>>>(W);
    inst_gemm_mma<<<dim3(NCHUNK, 4), 256, GEMM_SMEM>>>(labels);
    inst_reduce<<<1, 512>>>(out);
    mask_kernel<<<NPIX / 256, 256>>>(seg, masks);
    global_kernel<<<16, 256>>>(labels);
    sims_kernel<<<dim3(16, PP), 256>>>();
    boost_kernel<<<PP, 256>>>();
    local_kernel<<<dim3(BB, PP), 256>>>(labels, vmask, tmask);
    finalize_kernel<<<1, 1>>>(out);
}

// round 5
// speedup vs baseline: 1.3753x; 1.1973x over previous
#include <cuda_runtime.h>
#include <cuda_bf16.h>
#include <math.h>
#include <stdint.h>

#define BB 256
#define DD 512
#define PP 5
#define NC 11003
#define NCPAD 11008
#define SEGC 6
#define SCALE_ 28.0f
#define ALPHA_ 0.6f
#define BETA_ 0.4f
#define SP_ 10.0f
#define SN_ 40.0f

#define NCHUNK 172         // ceil(11008/64)
#define NPIX (1280*4096)   // B*P * H*H

// ---------------- device scratch (static; no allocation) ----------------
__device__ float g_XN[2*BB*DD];
__device__ float g_tnT[DD*BB];
__device__ float g_penN[PP*BB*DD];
__device__ float g_aeT[PP*DD*BB];
__device__ __align__(16) __nv_bfloat16 g_Ahi[2*BB*DD];
__device__ __align__(16) __nv_bfloat16 g_Alo[2*BB*DD];
__device__ __align__(16) __nv_bfloat16 g_Bhi[NCPAD*DD];
__device__ __align__(16) __nv_bfloat16 g_Blo[NCPAD*DD];
__device__ float g_chunkMax[NCHUNK*2*BB];   // chunk-major for coalesced reduce
__device__ float g_chunkSum[NCHUNK*2*BB];
__device__ float g_labLogit[2*BB];
__device__ float g_sims[PP*BB*BB];
__device__ int   g_boost1[PP*BB];
__device__ int   g_boost2[PP*BB];
__device__ int   g_vmInt, g_tmInt;
__device__ double g_accMask;
__device__ double g_accGlob;
__device__ double g_accLocal;

// ---------------- math helpers ----------------
__device__ __forceinline__ float softplus_f(float x) {
    if (x > 20.f) return x;
    if (x < -20.f) return __expf(x);
    return log1pf(__expf(x));
}
__device__ __forceinline__ double blockReduceD(double v, double* sred) {
    int t = threadIdx.x;
    sred[t] = v; __syncthreads();
    for (int s = blockDim.x >> 1; s > 0; s >>= 1) {
        if (t < s) sred[t] += sred[t + s];
        __syncthreads();
    }
    return sred[0];
}
__device__ __forceinline__ bool readMask(const uint8_t* m, int idx, int isInt) {
    return isInt ? (((const int*)m)[idx] != 0) : (m[idx] != 0);
}
__device__ __forceinline__ float rsqrt_nt(float s) {
    float inv = rsqrtf(s);
    return inv * (1.5f - 0.5f * s * inv * inv);
}

// bf16 HMMA: D(16x8,f32) += A(16x16,bf16) * B(16x8,bf16)
__device__ __forceinline__ void mma_bf16(float* c, const uint32_t* a, const uint32_t* b) {
    asm volatile(
        "mma.sync.aligned.m16n8k16.row.col.f32.bf16.bf16.f32 "
        "{%0,%1,%2,%3}, {%4,%5,%6,%7}, {%8,%9}, {%0,%1,%2,%3};"
        : "+f"(c[0]), "+f"(c[1]), "+f"(c[2]), "+f"(c[3])
        : "r"(a[0]), "r"(a[1]), "r"(a[2]), "r"(a[3]), "r"(b[0]), "r"(b[1]));
}
__device__ __forceinline__ void ldsm_x4(uint32_t& r0, uint32_t& r1, uint32_t& r2, uint32_t& r3, uint32_t addr) {
    asm volatile("ldmatrix.sync.aligned.m8n8.x4.shared.b16 {%0,%1,%2,%3}, [%4];"
                 : "=r"(r0), "=r"(r1), "=r"(r2), "=r"(r3) : "r"(addr));
}

// ---------------- detect mask dtype + zero accumulators ----------------
__global__ void detect_init_kernel(const uint8_t* __restrict__ vm, const uint8_t* __restrict__ tm) {
    __shared__ int s0, s1;
    if (threadIdx.x == 0) { s0 = 0; s1 = 0; g_accMask = 0.0; g_accGlob = 0.0; g_accLocal = 0.0; }
    __syncthreads();
    int a0 = 0, a1 = 0;
    for (int i = threadIdx.x; i < PP*BB; i += 256) {
        if (i & 3) { a0 |= vm[i]; a1 |= tm[i]; }
    }
    atomicOr(&s0, a0); atomicOr(&s1, a1);
    __syncthreads();
    if (threadIdx.x == 0) { g_vmInt = (s0 == 0) ? 1 : 0; g_tmInt = (s1 == 0) ? 1 : 0; }
}

// ---------------- normalize rows (+ bf16 hi/lo for v/t, transposed copies for tn, ae) ----------------
__global__ void normalize_kernel(const float* __restrict__ v, const float* __restrict__ t,
                                 const float* __restrict__ pe, const float* __restrict__ ae) {
    __shared__ float sred[256];
    int b = blockIdx.x;
    const float* src;
    float* dst = nullptr;
    float* dstT = nullptr;
    int tcol = 0;
    bool isXN = false;
    if (b < 256) { src = v + (size_t)b*DD; dst = g_XN + (size_t)b*DD; isXN = true; }
    else if (b < 512) { int r = b - 256; src = t + (size_t)r*DD; dst = g_XN + (size_t)b*DD; dstT = g_tnT; tcol = r; isXN = true; }
    else if (b < 512 + PP*BB) { int k = b - 512; src = pe + (size_t)k*DD; dst = g_penN + (size_t)k*DD; }
    else { int k = b - 512 - PP*BB; int p = k / BB; int rr = k % BB;
           src = ae + (size_t)k*DD; dstT = g_aeT + (size_t)p*DD*BB; tcol = rr; }

    float s = 0.f;
    for (int d = threadIdx.x; d < DD; d += 256) { float x = src[d]; s += x*x; }
    sred[threadIdx.x] = s; __syncthreads();
    for (int st = 128; st > 0; st >>= 1) { if (threadIdx.x < st) sred[threadIdx.x] += sred[threadIdx.x + st]; __syncthreads(); }
    float inv = rsqrt_nt(sred[0]);

    for (int d = threadIdx.x; d < DD; d += 256) {
        float x = src[d] * inv;
        if (dst)  dst[d] = x;
        if (dstT) dstT[d*BB + tcol] = x;
        if (isXN) {
            __nv_bfloat16 hi = __float2bfloat16(x);
            g_Ahi[(size_t)b*DD + d] = hi;
            g_Alo[(size_t)b*DD + d] = __float2bfloat16(x - __bfloat162float(hi));
        }
    }
}

// ---------------- transpose W -> bf16 hi/lo [c][d], pad cols to 11008 ----------------
__global__ void cvtW_kernel(const float* __restrict__ W) {
    __shared__ float tile[32][33];
    int tx = threadIdx.x & 31, ty = threadIdx.x >> 5;
    int c0 = blockIdx.x * 32, d0 = blockIdx.y * 32;
    #pragma unroll
    for (int i = 0; i < 4; i++) {
        int d = d0 + ty + i*8, c = c0 + tx;
        tile[ty + i*8][tx] = (c < NC) ? W[(size_t)d*NC + c] : 0.f;
    }
    __syncthreads();
    #pragma unroll
    for (int i = 0; i < 4; i++) {
        int cl = ty + i*8;
        int c = c0 + cl, d = d0 + tx;
        float v = tile[tx][cl];
        __nv_bfloat16 hi = __float2bfloat16(v);
        g_Bhi[(size_t)c*DD + d] = hi;
        g_Blo[(size_t)c*DD + d] = __float2bfloat16(v - __bfloat162float(hi));
    }
}

// ---------------- instance GEMM via mma.sync bf16 hi/lo + ldmatrix ----------------
// CTA tile M=128 x N=64, K staged 64 wide. 8 warps, each 16 rows x 64 cols.
// smem rows padded to 72 bf16 (144B): rows are 4 banks apart -> LDSM conflict-free.
#define SA_STRIDE 72
#define SMEM_AH 0
#define SMEM_AL 18432
#define SMEM_BH 36864
#define SMEM_BL 46080
#define GEMM_SMEM 55296

__global__ __launch_bounds__(256, 1) void inst_gemm_mma(const int* __restrict__ labels) {
    extern __shared__ __align__(16) char smem[];
    __nv_bfloat16* sAh = (__nv_bfloat16*)(smem + SMEM_AH);
    __nv_bfloat16* sAl = (__nv_bfloat16*)(smem + SMEM_AL);
    __nv_bfloat16* sBh = (__nv_bfloat16*)(smem + SMEM_BH);
    __nv_bfloat16* sBl = (__nv_bfloat16*)(smem + SMEM_BL);
    __shared__ float sInv[64];

    const int chunk = blockIdx.x;              // cols chunk*64
    const int rowBase = blockIdx.y * 128;
    const int colBase = chunk * 64;
    const int t = threadIdx.x;
    const int w = t >> 5, lane = t & 31;
    const int lr = lane & 7, mi = lane >> 3;

    const uint32_t sAhB = (uint32_t)__cvta_generic_to_shared(sAh);
    const uint32_t sAlB = (uint32_t)__cvta_generic_to_shared(sAl);
    const uint32_t sBhB = (uint32_t)__cvta_generic_to_shared(sBh);
    const uint32_t sBlB = (uint32_t)__cvta_generic_to_shared(sBl);

    // per-lane ldmatrix offsets (bytes)
    const uint32_t aoff = (uint32_t)((w*16 + lr + (mi & 1)*8) * SA_STRIDE + (mi >> 1)*8) * 2;
    uint32_t boff[4];
    #pragma unroll
    for (int q = 0; q < 4; q++)
        boff[q] = (uint32_t)((q*16 + (mi >> 1)*8 + lr) * SA_STRIDE + (mi & 1)*8) * 2;

    float acc[8][4];
    #pragma unroll
    for (int nf = 0; nf < 8; nf++)
        #pragma unroll
        for (int q = 0; q < 4; q++) acc[nf][q] = 0.f;

    float ss0 = 0.f, ss1 = 0.f;   // col sumsq: thread t owns col t>>3 (part t&7) and +32

    const __nv_bfloat16* Ahi = g_Ahi + (size_t)rowBase*DD;
    const __nv_bfloat16* Alo = g_Alo + (size_t)rowBase*DD;
    const __nv_bfloat16* Bhi = g_Bhi + (size_t)colBase*DD;
    const __nv_bfloat16* Blo = g_Blo + (size_t)colBase*DD;

    for (int kc = 0; kc < 8; kc++) {
        int k0g = kc * 64;
        // A tiles: 128 rows x 8 uint4 each (hi, lo)
        #pragma unroll
        for (int it = 0; it < 4; it++) {
            int idx = t + it*256;
            int row = idx >> 3, j = idx & 7;
            ((uint4*)sAh)[row*9 + j] = ((const uint4*)(Ahi + (size_t)row*DD + k0g))[j];
            ((uint4*)sAl)[row*9 + j] = ((const uint4*)(Alo + (size_t)row*DD + k0g))[j];
        }
        // B tiles + column sumsq from reconstructed values
        #pragma unroll
        for (int it = 0; it < 2; it++) {
            int idx = t + it*256;
            int row = idx >> 3, j = idx & 7;
            uint4 h = ((const uint4*)(Bhi + (size_t)row*DD + k0g))[j];
            uint4 l = ((const uint4*)(Blo + (size_t)row*DD + k0g))[j];
            ((uint4*)sBh)[row*9 + j] = h;
            ((uint4*)sBl)[row*9 + j] = l;
            float ss = 0.f;
            const uint32_t* hw = (const uint32_t*)&h;
            const uint32_t* lw = (const uint32_t*)&l;
            #pragma unroll
            for (int q = 0; q < 4; q++) {
                float2 fh = __bfloat1622float2(*(const __nv_bfloat162*)&hw[q]);
                float2 fl = __bfloat1622float2(*(const __nv_bfloat162*)&lw[q]);
                float v0 = fh.x + fl.x, v1 = fh.y + fl.y;
                ss += v0*v0 + v1*v1;
            }
            if (it == 0) ss0 += ss; else ss1 += ss;
        }
        __syncthreads();

        #pragma unroll
        for (int ks = 0; ks < 4; ks++) {
            uint32_t kadd = aoff + ks*32;
            uint32_t ah[4], al[4];
            ldsm_x4(ah[0], ah[1], ah[2], ah[3], sAhB + kadd);
            ldsm_x4(al[0], al[1], al[2], al[3], sAlB + kadd);
            #pragma unroll
            for (int q = 0; q < 4; q++) {
                uint32_t badd = boff[q] + ks*32;
                uint32_t bh[4], bl[4];
                ldsm_x4(bh[0], bh[1], bh[2], bh[3], sBhB + badd);
                ldsm_x4(bl[0], bl[1], bl[2], bl[3], sBlB + badd);
                mma_bf16(acc[2*q],   ah, bh);       // hi*hi
                mma_bf16(acc[2*q],   al, bh);       // lo*hi
                mma_bf16(acc[2*q],   ah, bl);       // hi*lo
                mma_bf16(acc[2*q+1], ah, bh+2);
                mma_bf16(acc[2*q+1], al, bh+2);
                mma_bf16(acc[2*q+1], ah, bl+2);
            }
        }
        __syncthreads();
    }

    // reduce column sumsq across the 8 part-threads (consecutive lanes) -> sInv
    #pragma unroll
    for (int off = 1; off < 8; off <<= 1) {
        ss0 += __shfl_xor_sync(0xffffffffu, ss0, off);
        ss1 += __shfl_xor_sync(0xffffffffu, ss1, off);
    }
    if ((t & 7) == 0) {
        sInv[t >> 3] = rsqrt_nt(ss0);
        sInv[(t >> 3) + 32] = rsqrt_nt(ss1);
    }
    __syncthreads();

    // epilogue: warp w owns rows w*16..+15; per row-half h, lanes hold 16 cols each
    const int g = lane >> 2, tig = lane & 3;
    #pragma unroll
    for (int h = 0; h < 2; h++) {
        int gr = rowBase + w*16 + g + h*8;
        int lab = labels[gr & 255];
        float lg[8][2];
        float m = -INFINITY;
        #pragma unroll
        for (int nf = 0; nf < 8; nf++) {
            #pragma unroll
            for (int j = 0; j < 2; j++) {
                int lc = nf*8 + tig*2 + j;
                int col = colBase + lc;
                float x;
                if (col < NC) {
                    x = SCALE_ * acc[nf][h*2 + j] * sInv[lc];
                    if (col == lab) g_labLogit[gr] = x;
                } else {
                    x = -INFINITY;
                }
                lg[nf][j] = x;
                m = fmaxf(m, x);
            }
        }
        m = fmaxf(m, __shfl_xor_sync(0xffffffffu, m, 1));
        m = fmaxf(m, __shfl_xor_sync(0xffffffffu, m, 2));
        float s = 0.f;
        #pragma unroll
        for (int nf = 0; nf < 8; nf++)
            #pragma unroll
            for (int j = 0; j < 2; j++) s += __expf(lg[nf][j] - m);
        s += __shfl_xor_sync(0xffffffffu, s, 1);
        s += __shfl_xor_sync(0xffffffffu, s, 2);
        if (tig == 0) {
            g_chunkMax[chunk*512 + gr] = m;
            g_chunkSum[chunk*512 + gr] = s;
        }
    }
}

// ---------------- instance loss reduce (coalesced chunk-major) ----------------
__global__ void inst_reduce(float* __restrict__ out) {
    __shared__ double sred[512];
    int t = threadIdx.x;
    float m = -INFINITY;
    for (int j = 0; j < NCHUNK; j++) m = fmaxf(m, g_chunkMax[j*512 + t]);
    float s = 0.f;
    for (int j = 0; j < NCHUNK; j++) s += g_chunkSum[j*512 + t] * __expf(g_chunkMax[j*512 + t] - m);
    float lse = m + logf(s);
    double v = (double)(lse - g_labLogit[t]);
    double tot = blockReduceD(v, sred);
    if (t == 0) out[0] = (float)(tot / 256.0);
}

// ---------------- mask loss ----------------
__global__ void mask_kernel(const float* __restrict__ seg, const int* __restrict__ masks) {
    __shared__ double sred[256];
    long long pix = (long long)blockIdx.x * 256 + threadIdx.x;
    double v = 0.0;
    if (pix < NPIX) {
        int n = (int)(pix >> 12);
        int hw = (int)(pix & 4095);
        const float* base = seg + (size_t)n * SEGC * 4096 + hw;
        float x[SEGC];
        float m = -INFINITY;
        #pragma unroll
        for (int c = 0; c < SEGC; c++) { x[c] = base[(size_t)c*4096]; m = fmaxf(m, x[c]); }
        float s = 0.f;
        #pragma unroll
        for (int c = 0; c < SEGC; c++) s += __expf(x[c] - m);
        int cls = masks[pix];
        v = (double)(m + logf(s) - x[cls]);
    }
    double tot = blockReduceD(v, sred);
    if (threadIdx.x == 0) atomicAdd(&g_accMask, tot);
}

// ---------------- global align ----------------
__global__ __launch_bounds__(256) void global_kernel(const int* __restrict__ labels) {
    __shared__ float sV[DD*17];
    __shared__ double sred[256];
    int rg = blockIdx.x;
    int j = threadIdx.x;

    for (int idx = j; idx < 16*DD; idx += 256) {
        int rr = idx / DD, d = idx % DD;
        sV[d*17 + rr] = g_XN[(size_t)(rg*16 + rr)*DD + d];
    }
    __syncthreads();

    float acc[16];
    #pragma unroll
    for (int rr = 0; rr < 16; rr++) acc[rr] = 0.f;
    for (int d = 0; d < DD; d++) {
        float b = g_tnT[d*BB + j];
        #pragma unroll
        for (int rr = 0; rr < 16; rr++) acc[rr] += sV[d*17 + rr] * b;
    }

    int labj = labels[j];
    double lsum = 0.0;
    #pragma unroll
    for (int rr = 0; rr < 16; rr++) {
        bool match = (labels[rg*16 + rr] == labj);
        float s = acc[rr];
        float val = match ? softplus_f(-SP_ * (s - ALPHA_)) : softplus_f(SN_ * (s - BETA_));
        lsum += (double)val;
    }
    double tot = blockReduceD(lsum, sred);
    if (j == 0) atomicAdd(&g_accGlob, tot);
}

// ---------------- part sims ----------------
__global__ __launch_bounds__(256) void sims_kernel() {
    __shared__ float sP[DD*17];
    int rg = blockIdx.x;
    int p = blockIdx.y;
    int j = threadIdx.x;

    for (int idx = j; idx < 16*DD; idx += 256) {
        int rr = idx / DD, d = idx % DD;
        sP[d*17 + rr] = g_penN[((size_t)p*BB + rg*16 + rr)*DD + d];
    }
    __syncthreads();

    float acc[16];
    #pragma unroll
    for (int rr = 0; rr < 16; rr++) acc[rr] = 0.f;
    const float* aT = g_aeT + (size_t)p*DD*BB;
    for (int d = 0; d < DD; d++) {
        float b = aT[d*BB + j];
        #pragma unroll
        for (int rr = 0; rr < 16; rr++) acc[rr] += sP[d*17 + rr] * b;
    }
    float* S = g_sims + (size_t)p*BB*BB;
    #pragma unroll
    for (int rr = 0; rr < 16; rr++) S[(size_t)(rg*16 + rr)*BB + j] = acc[rr];
}

// ---------------- boost via rank counts ----------------
__global__ void boost_kernel() {
    __shared__ float srow[BB], scol[BB];
    int p = blockIdx.x;
    int c = threadIdx.x;
    const float* S = g_sims + (size_t)p*BB*BB;
    srow[c] = S[(size_t)p*BB + c];
    scol[c] = S[(size_t)c*BB + p];
    __syncthreads();

    float vr = srow[c];
    int cnt = 0;
    for (int k = 0; k < BB; k++) { float o = srow[k]; cnt += (o > vr) || (o == vr && k < c); }
    bool inRow = cnt < 8;
    cnt = 0;
    for (int r = 0; r < BB; r++) { float o = S[(size_t)r*BB + c]; cnt += (o > vr) || (o == vr && r < p); }
    bool inCol = cnt < 8;
    g_boost1[p*BB + c] = (inRow && inCol) ? 1 : 0;

    float vc = scol[c];
    cnt = 0;
    for (int k = 0; k < BB; k++) { float o = scol[k]; cnt += (o > vc) || (o == vc && k < c); }
    bool inColP = cnt < 8;
    cnt = 0;
    for (int cc = 0; cc < BB; cc++) { float o = S[(size_t)c*BB + cc]; cnt += (o > vc) || (o == vc && cc < p); }
    bool inRowR = cnt < 8;
    g_boost2[p*BB + c] = (inColP && inRowR) ? 1 : 0;
}

// ---------------- local align loss ----------------
__global__ void local_kernel(const int* __restrict__ labels,
                             const uint8_t* __restrict__ vmask,
                             const uint8_t* __restrict__ tmask) {
    __shared__ double sred[256];
    int r = blockIdx.x;
    int p = blockIdx.y;
    int c = threadIdx.x;

    int vmInt = g_vmInt, tmInt = g_tmInt;
    float s = g_sims[((size_t)p*BB + r)*BB + c];
    bool match = (labels[r] == labels[c]);
    float Lp = softplus_f(-SP_ * (s - ALPHA_));
    float Ln = softplus_f(SN_ * (s - BETA_));

    bool pmr = readMask(vmask, r*PP + p, vmInt);
    bool pmc = readMask(vmask, c*PP + p, vmInt);
    bool amc = readMask(tmask, c*PP + p, tmInt);

    double val = 0.0;
    if (pmr && amc) val += (double)((match || g_boost1[p*BB + c]) ? Lp : Ln);
    if (pmr && pmc && amc) val += (double)((match || g_boost2[p*BB + r]) ? Lp : Ln);

    double tot = blockReduceD(val, sred);
    if (c == 0) atomicAdd(&g_accLocal, tot);
}

__global__ void finalize_kernel(float* __restrict__ out) {
    out[1] = (float)(5.0 * g_accMask / ((double)NPIX));
    out[2] = (float)(2.0 * g_accGlob / 256.0);
    out[3] = (float)(g_accLocal / (256.0 * 5.0));
}

// ---------------- launch ----------------
extern "C" void kernel_launch(void* const* d_in, const int* in_sizes, int n_in,
                              void* d_out, int out_size) {
    const float* visual    = (const float*)d_in[0];
    const float* textual   = (const float*)d_in[1];
    const float* part      = (const float*)d_in[2];
    const float* attribute = (const float*)d_in[3];
    const float* seg       = (const float*)d_in[4];
    const float* W         = (const float*)d_in[5];
    const int*   labels    = (const int*)d_in[6];
    const int*   masks     = (const int*)d_in[7];
    const uint8_t* vmask   = (const uint8_t*)d_in[8];
    const uint8_t* tmask   = (const uint8_t*)d_in[9];
    float* out = (float*)d_out;

    static cudaStream_t s2;
    static cudaEvent_t evFork, evJoin;
    static int initOnce = 0;
    if (!initOnce) {
        cudaFuncSetAttribute(inst_gemm_mma, cudaFuncAttributeMaxDynamicSharedMemorySize, GEMM_SMEM);
        cudaStreamCreateWithFlags(&s2, cudaStreamNonBlocking);
        cudaEventCreateWithFlags(&evFork, cudaEventDisableTiming);
        cudaEventCreateWithFlags(&evJoin, cudaEventDisableTiming);
        initOnce = 1;
    }

    // stream 0: GEMM chain (gemm = launch index 3 -> profiled by ncu)
    detect_init_kernel<<<1, 256>>>(vmask, tmask);
    normalize_kernel<<<512 + 2*PP*BB, 256>>>(visual, textual, part, attribute);
    cudaEventRecord(evFork, 0);
    cvtW_kernel<<<dim3(NCPAD/32, DD/32), 256>>>(W);
    inst_gemm_mma<<<dim3(NCHUNK, 4), 256, GEMM_SMEM>>>(labels);

    // stream s2: independent memory/ALU-bound losses, overlapped with GEMM
    cudaStreamWaitEvent(s2, evFork, 0);
    mask_kernel<<<NPIX / 256, 256, 0, s2>>>(seg, masks);
    global_kernel<<<16, 256, 0, s2>>>(labels);
    sims_kernel<<<dim3(16, PP), 256, 0, s2>>>();
    boost_kernel<<<PP, 256, 0, s2>>>();
    local_kernel<<<dim3(BB, PP), 256, 0, s2>>>(labels, vmask, tmask);
    cudaEventRecord(evJoin, s2);

    inst_reduce<<<1, 512>>>(out);
    cudaStreamWaitEvent(0, evJoin, 0);
    finalize_kernel<<<1, 1>>>(out);
}